// round 1
// baseline (speedup 1.0000x reference)
#include <cuda_runtime.h>
#include <cuda_bf16.h>

// HSMNet cost-volume + channel-sum + softmax disparity regression, fused.
// Shapes fixed by the problem: B=4, C=32, H=80, W=160, D=24. Output [B,H,W] f32.
//
// One CTA per (b,h) row: 320 CTAs x 160 threads (thread = one w).
// tgt row staged in smem [C][W] (20 KB): conflict-free stores and reads.
// ref[b,:,h,w] held in 32 registers. Online softmax over d (branchless).

#define Bc 4
#define Cc 32
#define Hc 80
#define Wc 160
#define Dc 24

__global__ __launch_bounds__(Wc)
void hsm_dispreg_kernel(const float* __restrict__ ref,
                        const float* __restrict__ tgt,
                        float* __restrict__ out)
{
    __shared__ float st[Cc * Wc];   // tgt[b, c, h, :] for this row

    const int h = blockIdx.x;
    const int b = blockIdx.y;
    const int w = threadIdx.x;      // 0..159

    // Load ref channel vector into registers, stage tgt row into smem.
    float r[Cc];
#pragma unroll
    for (int c = 0; c < Cc; ++c) {
        const int off = ((b * Cc + c) * Hc + h) * Wc + w;  // fits in int
        r[c] = ref[off];
        st[c * Wc + w] = tgt[off];
    }
    __syncthreads();

    // Online softmax over d of v_d = sum_c |ref[c][w] - tgt[c][w-d]| (0 if d > w),
    // simultaneously accumulating the disparity expectation numerator.
    float m = -3.0e38f;   // running max
    float s = 0.0f;       // running sum of exp
    float num = 0.0f;     // running sum of d * exp

#pragma unroll 1
    for (int d = 0; d < Dc; ++d) {
        float v = 0.0f;
        if (w >= d) {
            const float* tp = &st[w - d];
            // 4 independent accumulator chains to break the RAW latency chain.
            float a0 = 0.f, a1 = 0.f, a2 = 0.f, a3 = 0.f;
#pragma unroll
            for (int c = 0; c < Cc; c += 4) {
                a0 += fabsf(r[c + 0] - tp[(c + 0) * Wc]);
                a1 += fabsf(r[c + 1] - tp[(c + 1) * Wc]);
                a2 += fabsf(r[c + 2] - tp[(c + 2) * Wc]);
                a3 += fabsf(r[c + 3] - tp[(c + 3) * Wc]);
            }
            v = (a0 + a1) + (a2 + a3);
        }
        const float mn = fmaxf(m, v);
        const float rs = __expf(m - mn);   // rescale factor for old accumulators
        const float e  = __expf(v - mn);
        s   = s   * rs + e;
        num = num * rs + (float)d * e;
        m = mn;
    }

    out[(b * Hc + h) * Wc + w] = num / s;
}

extern "C" void kernel_launch(void* const* d_in, const int* in_sizes, int n_in,
                              void* d_out, int out_size)
{
    const float* ref = (const float*)d_in[0];
    const float* tgt = (const float*)d_in[1];
    // d_in[2] is maxdisp (=24), baked in as a compile-time constant.
    float* out = (float*)d_out;

    dim3 grid(Hc, Bc);   // 80 x 4 = 320 CTAs
    hsm_dispreg_kernel<<<grid, Wc>>>(ref, tgt, out);
}